// round 16
// baseline (speedup 1.0000x reference)
#include <cuda_runtime.h>
#include <cuda_fp16.h>
#include <math.h>
#include <stdint.h>

#define QLEN   512
#define MLEN   512
#define KLEN   1024
#define BSZ    16
#define DM     1024
#define NHEAD  16
#define DHEAD  64
#define HID    1024
#define DI     4096
#define NTOK   (QLEN*BSZ)
#define KTOK   (KLEN*BSZ)
#define H3     3072
#define NBN    (BSZ*NHEAD)
#define THEME_SIZE 1000
#define THEME_PAD  1024
#define TCAT   512

// ---------------- scratch ----------------
__device__ float g_pos    [KLEN*DM];
__device__ float g_x      [NTOK*DM];
__device__ float g_scores [(size_t)NBN*QLEN*KLEN];   // aliased fp16
__device__ float g_bdbuf  [(size_t)NBN*QLEN*KLEN];   // aliased fp16
__device__ float g_h      [NTOK*DM];
__device__ float g_tmp    [NTOK*DM];
__device__ float g_theme  [THEME_PAD*DM];
__device__ float g_rolecat[64*256];
__device__ float g_themecat[THEME_PAD*TCAT];
__device__ float g_pooled [BSZ*DM];
__device__ unsigned g_kbits[BSZ*32];
// fp16 buffers
__device__ __half g_ah [(size_t)KTOK*DM];
__device__ __half g_al [(size_t)KTOK*DM];     // theme GEMM lo part only
__device__ __half g_ah2[(size_t)NTOK*DI];
__device__ __half g_bth[(size_t)DI*DM];
__device__ __half g_hh [(size_t)KTOK*H3];
__device__ __half g_rhh[KLEN*HID];
__device__ __half g_posh[KLEN*DM];
__device__ __half g_ph [(size_t)NBN*QLEN*KLEN];
__device__ __half g_vth[(size_t)NBN*DHEAD*KLEN];
__device__ float g_bwk[NBN*KLEN];
__device__ float g_brr[NHEAD*KLEN];

__device__ __forceinline__ uint32_t smem_u32(const void* p) {
    uint32_t a;
    asm("{ .reg .u64 t; cvta.to.shared.u64 t, %1; cvt.u32.u64 %0, t; }" : "=r"(a) : "l"(p));
    return a;
}
__device__ __forceinline__ void ldsm_x4(uint32_t& r0, uint32_t& r1, uint32_t& r2,
                                        uint32_t& r3, uint32_t addr) {
    asm volatile("ldmatrix.sync.aligned.m8n8.x4.shared.b16 {%0,%1,%2,%3}, [%4];"
                 : "=r"(r0), "=r"(r1), "=r"(r2), "=r"(r3) : "r"(addr));
}
__device__ __forceinline__ void ldsm_x2(uint32_t& r0, uint32_t& r1, uint32_t addr) {
    asm volatile("ldmatrix.sync.aligned.m8n8.x2.shared.b16 {%0,%1}, [%2];"
                 : "=r"(r0), "=r"(r1) : "r"(addr));
}
__device__ __forceinline__ void mma_f16(float* c, const uint32_t* a, const uint32_t* b) {
    asm volatile(
        "mma.sync.aligned.m16n8k16.row.col.f32.f16.f16.f32 "
        "{%0,%1,%2,%3}, {%4,%5,%6,%7}, {%8,%9}, {%0,%1,%2,%3};"
        : "+f"(c[0]), "+f"(c[1]), "+f"(c[2]), "+f"(c[3])
        : "r"(a[0]), "r"(a[1]), "r"(a[2]), "r"(a[3]), "r"(b[0]), "r"(b[1]));
}
__device__ __forceinline__ void cp16(uint32_t dst, const void* src) {
    asm volatile("cp.async.cg.shared.global [%0], [%1], 16;" :: "r"(dst), "l"(src));
}
#define CP_COMMIT() asm volatile("cp.async.commit_group;" ::: "memory")
#define CP_WAIT1()  asm volatile("cp.async.wait_group 1;" ::: "memory")
#define CP_WAIT0()  asm volatile("cp.async.wait_group 0;" ::: "memory")

__device__ __forceinline__ void split_write(__half* __restrict__ H,
                                            __half* __restrict__ L,
                                            size_t idx, float v0, float v1) {
    __half h0 = __float2half_rn(v0), h1 = __float2half_rn(v1);
    __half l0 = __float2half_rn(v0 - __half2float(h0));
    __half l1 = __float2half_rn(v1 - __half2float(h1));
    ushort2 hp; hp.x = __half_as_ushort(h0); hp.y = __half_as_ushort(h1);
    ushort2 lp; lp.x = __half_as_ushort(l0); lp.y = __half_as_ushort(l1);
    *(ushort2*)(H + idx) = hp;
    *(ushort2*)(L + idx) = lp;
}
__device__ __forceinline__ void hf_write2(__half* __restrict__ P, size_t idx,
                                          float v0, float v1) {
    ushort2 w;
    w.x = __half_as_ushort(__float2half_rn(v0));
    w.y = __half_as_ushort(__float2half_rn(v1));
    *(ushort2*)(P + idx) = w;
}

// ======== mma_gemm64: single-pass fp16, K-chunk 64, 2 stages, 2 CTAs/SM ========
// OUT: 0 fp32 C; 3 single fp16 (Ho).
#define SSTR4 72
#define ARR4 (128*SSTR4*2)        // 18432 B
#define STG4 (2*ARR4)             // 36864
#define GSMEM4 (2*STG4)           // 73728

template<int ACT, int OUT>
__global__ __launch_bounds__(256, 2) void mma_gemm64(
    const __half* __restrict__ Ah, const __half* __restrict__ Bh,
    const float* __restrict__ bias, float* __restrict__ C,
    __half* __restrict__ Ho,
    int M, int N, int K, int ldc)
{
    extern __shared__ char dsm[];
    uint32_t sb = smem_u32(dsm);

    int tid = threadIdx.x, lane = tid & 31, wid = tid >> 5;
    int row0 = blockIdx.y * 128, col0 = blockIdx.x * 128;
    int wm = (wid >> 2) * 64;
    int wn = (wid & 3) * 32;

    float acc[4][4][4];
    #pragma unroll
    for (int i = 0; i < 4; i++)
        #pragma unroll
        for (int j = 0; j < 4; j++)
            #pragma unroll
            for (int u = 0; u < 4; u++) acc[i][j][u] = 0.f;

    int rb = tid >> 3;              // 0..31
    int cb = (tid & 7) * 8;         // elem in 64-wide chunk
    uint32_t sm_off = (uint32_t)(rb * SSTR4 + cb) * 2;

    int nch = K >> 6;

    #define ISSUE64(ch, s) do { \
        uint32_t base = sb + (s) * STG4 + sm_off; \
        size_t goff = (size_t)(ch) * 64 + cb; \
        _Pragma("unroll") \
        for (int k4 = 0; k4 < 4; k4++) { \
            int row = rb + k4 * 32; \
            uint32_t so = base + (uint32_t)(k4 * 32 * SSTR4) * 2; \
            size_t ga = (size_t)(row0 + row) * K + goff; \
            size_t gb = (size_t)(col0 + row) * K + goff; \
            cp16(so,        Ah + ga); \
            cp16(so + ARR4, Bh + gb); \
        } \
    } while (0)

    ISSUE64(0, 0); CP_COMMIT();
    if (nch > 1) ISSUE64(1, 1);
    CP_COMMIT();

    uint32_t a_off = (uint32_t)((wm + (lane & 15)) * SSTR4 + (lane >> 4) * 8) * 2;
    uint32_t b_off = (uint32_t)((wn + (lane & 7)) * SSTR4 + ((lane >> 3) & 1) * 8) * 2;

    for (int ch = 0; ch < nch; ch++) {
        int s = ch & 1;
        CP_WAIT1();
        __syncthreads();

        uint32_t sA_b = sb + s * STG4;
        uint32_t sB_b = sA_b + ARR4;

        #pragma unroll
        for (int ks = 0; ks < 64; ks += 16) {
            uint32_t a[4][4], bh[4][2];
            #pragma unroll
            for (int mt = 0; mt < 4; mt++) {
                uint32_t ao = a_off + (uint32_t)(mt * 16 * SSTR4 + ks) * 2;
                ldsm_x4(a[mt][0], a[mt][1], a[mt][2], a[mt][3], sA_b + ao);
            }
            #pragma unroll
            for (int nt = 0; nt < 4; nt++) {
                uint32_t bo = b_off + (uint32_t)(nt * 8 * SSTR4 + ks) * 2;
                ldsm_x2(bh[nt][0], bh[nt][1], sB_b + bo);
            }
            #pragma unroll
            for (int mt = 0; mt < 4; mt++)
                #pragma unroll
                for (int nt = 0; nt < 4; nt++)
                    mma_f16(acc[mt][nt], a[mt], bh[nt]);
        }
        __syncthreads();
        if (ch + 2 < nch) ISSUE64(ch + 2, s);
        CP_COMMIT();
    }

    int gr = lane >> 2, gc = (lane & 3) * 2;
    #pragma unroll
    for (int mt = 0; mt < 4; mt++) {
        int r0 = row0 + wm + mt*16 + gr;
        #pragma unroll
        for (int nt = 0; nt < 4; nt++) {
            int c = col0 + wn + nt*8 + gc;
            float b0 = 0.f, b1 = 0.f;
            if (bias) { b0 = bias[c]; b1 = bias[c+1]; }
            float v0 = acc[mt][nt][0] + b0, v1 = acc[mt][nt][1] + b1;
            float v2 = acc[mt][nt][2] + b0, v3 = acc[mt][nt][3] + b1;
            if (ACT == 1) {
                v0 = fmaxf(v0,0.f); v1 = fmaxf(v1,0.f);
                v2 = fmaxf(v2,0.f); v3 = fmaxf(v3,0.f);
            }
            size_t i0 = (size_t)r0 * ldc + c;
            size_t i1 = (size_t)(r0 + 8) * ldc + c;
            if (OUT == 0) {
                float2 w0 = {v0, v1}, w1 = {v2, v3};
                *(float2*)(C + i0) = w0;
                *(float2*)(C + i1) = w1;
            } else {
                hf_write2(Ho, i0, v0, v1);
                hf_write2(Ho, i1, v2, v3);
            }
        }
    }
}

// ======== theme GEMM (2-pass, kept from R14) ========
#define SSTR3 40
#define ARR3 (128*SSTR3*2)
#define STG3 (3*ARR3)
#define GSMEM3 (2*STG3)

__global__ __launch_bounds__(256, 2) void mma_gemm_theme(
    const __half* __restrict__ Ah, const __half* __restrict__ Al,
    const __half* __restrict__ Bh,
    const float* __restrict__ bias, float* __restrict__ C,
    int M, int N, int K, int ldc)
{
    extern __shared__ char dsm[];
    uint32_t sb = smem_u32(dsm);

    int tid = threadIdx.x, lane = tid & 31, wid = tid >> 5;
    int row0 = blockIdx.y * 128, col0 = blockIdx.x * 128;
    int wm = (wid >> 2) * 64;
    int wn = (wid & 3) * 32;

    float acc[4][4][4];
    #pragma unroll
    for (int i = 0; i < 4; i++)
        #pragma unroll
        for (int j = 0; j < 4; j++)
            #pragma unroll
            for (int u = 0; u < 4; u++) acc[i][j][u] = 0.f;

    int rb = tid >> 2;
    int cb = (tid & 3) * 8;
    uint32_t sm_off = (uint32_t)(rb * SSTR3 + cb) * 2;

    int nch = K >> 5;

    #define ISSUE3(ch, s) do { \
        uint32_t base = sb + (s) * STG3 + sm_off; \
        size_t goff = (size_t)(ch) * 32 + cb; \
        _Pragma("unroll") \
        for (int k2 = 0; k2 < 2; k2++) { \
            int row = rb + k2 * 64; \
            uint32_t so = base + (uint32_t)(k2 * 64 * SSTR3) * 2; \
            size_t ga = (size_t)(row0 + row) * K + goff; \
            size_t gb = (size_t)(col0 + row) * K + goff; \
            cp16(so,           Ah + ga); \
            cp16(so + ARR3,    Al + ga); \
            cp16(so + 2*ARR3,  Bh + gb); \
        } \
    } while (0)

    ISSUE3(0, 0); CP_COMMIT();
    if (nch > 1) ISSUE3(1, 1);
    CP_COMMIT();

    uint32_t a_off = (uint32_t)((wm + (lane & 15)) * SSTR3 + (lane >> 4) * 8) * 2;
    uint32_t b_off = (uint32_t)((wn + (lane & 7)) * SSTR3 + ((lane >> 3) & 1) * 8) * 2;

    for (int ch = 0; ch < nch; ch++) {
        int s = ch & 1;
        CP_WAIT1();
        __syncthreads();

        uint32_t sAh_b = sb + s * STG3;
        uint32_t sAl_b = sAh_b + ARR3;
        uint32_t sBh_b = sAh_b + 2*ARR3;

        #pragma unroll
        for (int ks = 0; ks < 32; ks += 16) {
            uint32_t ah[4][4], al[4][4], bh[4][2];
            #pragma unroll
            for (int mt = 0; mt < 4; mt++) {
                uint32_t ao = a_off + (uint32_t)(mt * 16 * SSTR3 + ks) * 2;
                ldsm_x4(ah[mt][0], ah[mt][1], ah[mt][2], ah[mt][3], sAh_b + ao);
                ldsm_x4(al[mt][0], al[mt][1], al[mt][2], al[mt][3], sAl_b + ao);
            }
            #pragma unroll
            for (int nt = 0; nt < 4; nt++) {
                uint32_t bo = b_off + (uint32_t)(nt * 8 * SSTR3 + ks) * 2;
                ldsm_x2(bh[nt][0], bh[nt][1], sBh_b + bo);
            }
            #pragma unroll
            for (int mt = 0; mt < 4; mt++)
                #pragma unroll
                for (int nt = 0; nt < 4; nt++) {
                    mma_f16(acc[mt][nt], ah[mt], bh[nt]);
                    mma_f16(acc[mt][nt], al[mt], bh[nt]);
                }
        }
        __syncthreads();
        if (ch + 2 < nch) ISSUE3(ch + 2, s);
        CP_COMMIT();
    }

    int gr = lane >> 2, gc = (lane & 3) * 2;
    #pragma unroll
    for (int mt = 0; mt < 4; mt++) {
        int r0 = row0 + wm + mt*16 + gr;
        #pragma unroll
        for (int nt = 0; nt < 4; nt++) {
            int c = col0 + wn + nt*8 + gc;
            float b0 = bias[c], b1 = bias[c+1];
            float v0 = tanhf(acc[mt][nt][0] + b0), v1 = tanhf(acc[mt][nt][1] + b1);
            float v2 = tanhf(acc[mt][nt][2] + b0), v3 = tanhf(acc[mt][nt][3] + b1);
            float2 w0 = {v0, v1}, w1 = {v2, v3};
            *(float2*)(C + (size_t)r0 * ldc + c) = w0;
            *(float2*)(C + (size_t)(r0 + 8) * ldc + c) = w1;
        }
    }
}

// ======== fused AC+BD score kernel: single fp16 operands, 2 CTAs/SM ========
#define SSTR2 72
#define SC_ARR (128*SSTR2*2)
#define SC_SMEM (3*SC_ARR)
__global__ __launch_bounds__(256, 2) void k_score2(
    const __half* __restrict__ hh, const __half* __restrict__ rhh,
    __half* __restrict__ outAC, __half* __restrict__ outBD)
{
    extern __shared__ char dsm[];
    uint32_t sb = smem_u32(dsm);
    int tid = threadIdx.x, lane = tid & 31, wid = tid >> 5;
    int col0 = blockIdx.x * 128, row0 = blockIdx.y * 128, bn = blockIdx.z;
    int b = bn >> 4, n = bn & 15;
    size_t lda = (size_t)BSZ * H3;
    size_t qbase = ((size_t)(MLEN + row0) * BSZ + b) * H3 + n * 64;
    size_t kbase = ((size_t)col0 * BSZ + b) * H3 + HID + n * 64;
    size_t rbase = (size_t)col0 * HID + n * 64;
    int wm = (wid >> 2) * 64, wn = (wid & 3) * 32;

    {
        int rb = tid >> 3;
        int cbo = (tid & 7) * 8;
        uint32_t so0 = sb + (uint32_t)(rb * SSTR2 + cbo) * 2;
        #pragma unroll
        for (int k4 = 0; k4 < 4; k4++) {
            int row = rb + k4 * 32;
            uint32_t so = so0 + (uint32_t)(k4 * 32 * SSTR2) * 2;
            cp16(so,            hh + qbase + (size_t)row * lda + cbo);
            cp16(so + SC_ARR,   hh + kbase + (size_t)row * lda + cbo);
            cp16(so + 2*SC_ARR, rhh + rbase + (size_t)row * HID + cbo);
        }
    }
    CP_COMMIT(); CP_WAIT0();
    __syncthreads();

    float accK[4][4][4], accR[4][4][4];
    #pragma unroll
    for (int i = 0; i < 4; i++)
        #pragma unroll
        for (int j = 0; j < 4; j++)
            #pragma unroll
            for (int u = 0; u < 4; u++) { accK[i][j][u] = 0.f; accR[i][j][u] = 0.f; }

    uint32_t a_off = (uint32_t)((wm + (lane & 15)) * SSTR2 + (lane >> 4) * 8) * 2;
    uint32_t b_off = (uint32_t)((wn + (lane & 7)) * SSTR2 + ((lane >> 3) & 1) * 8) * 2;
    uint32_t sQ = sb, sK = sb + SC_ARR, sR = sb + 2*SC_ARR;

    #pragma unroll
    for (int ks = 0; ks < 64; ks += 16) {
        uint32_t a[4][4], bh[4][2];
        #pragma unroll
        for (int mt = 0; mt < 4; mt++) {
            uint32_t ao = a_off + (uint32_t)(mt * 16 * SSTR2 + ks) * 2;
            ldsm_x4(a[mt][0], a[mt][1], a[mt][2], a[mt][3], sQ + ao);
        }
        #pragma unroll
        for (int nt = 0; nt < 4; nt++) {
            uint32_t bo = b_off + (uint32_t)(nt * 8 * SSTR2 + ks) * 2;
            ldsm_x2(bh[nt][0], bh[nt][1], sK + bo);
        }
        #pragma unroll
        for (int mt = 0; mt < 4; mt++)
            #pragma unroll
            for (int nt = 0; nt < 4; nt++)
                mma_f16(accK[mt][nt], a[mt], bh[nt]);
        #pragma unroll
        for (int nt = 0; nt < 4; nt++) {
            uint32_t bo = b_off + (uint32_t)(nt * 8 * SSTR2 + ks) * 2;
            ldsm_x2(bh[nt][0], bh[nt][1], sR + bo);
        }
        #pragma unroll
        for (int mt = 0; mt < 4; mt++)
            #pragma unroll
            for (int nt = 0; nt < 4; nt++)
                mma_f16(accR[mt][nt], a[mt], bh[nt]);
    }

    int gr = lane >> 2, gc = (lane & 3) * 2;
    #pragma unroll
    for (int mt = 0; mt < 4; mt++) {
        int r0 = row0 + wm + mt*16 + gr;
        #pragma unroll
        for (int nt = 0; nt < 4; nt++) {
            int c = col0 + wn + nt*8 + gc;
            size_t i0 = ((size_t)bn*QLEN + r0)*KLEN + c;
            size_t i1 = ((size_t)bn*QLEN + r0 + 8)*KLEN + c;
            hf_write2(outAC, i0, accK[mt][nt][0], accK[mt][nt][1]);
            hf_write2(outAC, i1, accK[mt][nt][2], accK[mt][nt][3]);
            hf_write2(outBD, i0, accR[mt][nt][0], accR[mt][nt][1]);
            hf_write2(outBD, i1, accR[mt][nt][2], accR[mt][nt][3]);
        }
    }
}

// -------- PV mma: P fp16 x V fp16, writes single-fp16 vec ----------
#define SSTR 40
__global__ __launch_bounds__(256, 2) void k_pv_mma(
    const __half* __restrict__ ph, const __half* __restrict__ vth,
    __half* __restrict__ AH)
{
    __shared__ __align__(16) __half sA[128*SSTR];
    __shared__ __align__(16) __half sB[64*SSTR];
    int tid = threadIdx.x, lane = tid & 31, wid = tid >> 5;
    int row0 = blockIdx.x * 128, bn = blockIdx.y;
    int b = bn >> 4, n = bn & 15;
    int wm = (wid >> 1) * 32, wn = (wid & 1) * 32;

    float acc[2][4][4];
    #pragma unroll
    for (int i = 0; i < 2; i++)
        #pragma unroll
        for (int j = 0; j < 4; j++)
            #pragma unroll
            for (int u = 0; u < 4; u++) acc[i][j][u] = 0.f;

    int gr0 = tid >> 2, gc0 = (tid & 3) * 8;
    int gr1 = (tid + 256) >> 2;
    int rB = tid >> 2, cB = (tid & 3) * 8;

    size_t abase = ((size_t)bn * QLEN + row0) * KLEN;
    size_t bbase = (size_t)bn * DHEAD * KLEN;

    uint32_t sA_b = smem_u32(sA), sB_b = smem_u32(sB);
    uint32_t a_off = (uint32_t)((wm + (lane & 15)) * SSTR + (lane >> 4) * 8) * 2;
    uint32_t b_off = (uint32_t)((wn + (lane & 7)) * SSTR + ((lane >> 3) & 1) * 8) * 2;

    uint4 pA[2], pB;
    #define PVLOAD(ch) do { \
        size_t a0o = abase + (size_t)gr0 * KLEN + (ch)*32 + gc0; \
        size_t a1o = abase + (size_t)gr1 * KLEN + (ch)*32 + gc0; \
        size_t b0o = bbase + (size_t)rB * KLEN + (ch)*32 + cB; \
        pA[0] = *(const uint4*)(ph + a0o);  pA[1] = *(const uint4*)(ph + a1o); \
        pB = *(const uint4*)(vth + b0o); \
    } while (0)

    PVLOAD(0);
    for (int ch = 0; ch < 32; ch++) {
        *(uint4*)&sA[gr0*SSTR + gc0] = pA[0]; *(uint4*)&sA[gr1*SSTR + gc0] = pA[1];
        if (rB < 64) *(uint4*)&sB[rB*SSTR + cB] = pB;
        __syncthreads();
        if (ch + 1 < 32) PVLOAD(ch + 1);

        #pragma unroll
        for (int ks = 0; ks < 32; ks += 16) {
            uint32_t a[2][4], bh[4][2];
            #pragma unroll
            for (int mt = 0; mt < 2; mt++) {
                uint32_t ao = a_off + (uint32_t)(mt * 16 * SSTR + ks) * 2;
                ldsm_x4(a[mt][0], a[mt][1], a[mt][2], a[mt][3], sA_b + ao);
            }
            #pragma unroll
            for (int nt = 0; nt < 4; nt++) {
                uint32_t bo = b_off + (uint32_t)(nt * 8 * SSTR + ks) * 2;
                ldsm_x2(bh[nt][0], bh[nt][1], sB_b + bo);
            }
            #pragma unroll
            for (int mt = 0; mt < 2; mt++)
                #pragma unroll
                for (int nt = 0; nt < 4; nt++)
                    mma_f16(acc[mt][nt], a[mt], bh[nt]);
        }
        __syncthreads();
    }

    int gr = lane >> 2, gc = (lane & 3) * 2;
    #pragma unroll
    for (int mt = 0; mt < 2; mt++) {
        int m = row0 + wm + mt*16 + gr;
        #pragma unroll
        for (int nt = 0; nt < 4; nt++) {
            int d = wn + nt*8 + gc;
            size_t i0 = ((size_t)m*BSZ + b)*HID + n*64 + d;
            size_t i1 = ((size_t)(m+8)*BSZ + b)*HID + n*64 + d;
            hf_write2(AH, i0, acc[mt][nt][0], acc[mt][nt][1]);
            hf_write2(AH, i1, acc[mt][nt][2], acc[mt][nt][3]);
        }
    }
}

// ---------------- converts / splits ----------------
__global__ __launch_bounds__(256) void k_split_a(
    const float* __restrict__ X, __half* __restrict__ H,
    __half* __restrict__ L, int n)
{
    int i = (blockIdx.x * 256 + threadIdx.x) * 4;
    if (i >= n) return;
    float4 v = *(const float4*)(X + i);
    split_write(H, L, i, v.x, v.y);
    split_write(H, L, i + 2, v.z, v.w);
}
__global__ __launch_bounds__(256) void k_tohalf(
    const float* __restrict__ X, __half* __restrict__ H, int n)
{
    int i = (blockIdx.x * 256 + threadIdx.x) * 4;
    if (i >= n) return;
    float4 v = *(const float4*)(X + i);
    hf_write2(H, i, v.x, v.y);
    hf_write2(H, i + 2, v.z, v.w);
}

__global__ void k_split_bt(const float* __restrict__ B, __half* __restrict__ H,
                           int K, int N)
{
    __shared__ float tile[32][33];
    int k0 = blockIdx.y * 32, n0 = blockIdx.x * 32;
    int tx = threadIdx.x, ty = threadIdx.y;
    #pragma unroll
    for (int j = 0; j < 32; j += 8)
        tile[ty + j][tx] = B[(size_t)(k0 + ty + j) * N + n0 + tx];
    __syncthreads();
    #pragma unroll
    for (int j = 0; j < 32; j += 8) {
        size_t o = (size_t)(n0 + ty + j) * K + k0 + tx;
        H[o] = __float2half_rn(tile[tx][ty + j]);
    }
}

__global__ void k_vt(const __half* __restrict__ hh, __half* __restrict__ vth)
{
    __shared__ __half tile[32][33];
    int j0 = blockIdx.x * 32, d0 = blockIdx.y * 32, bn = blockIdx.z;
    int b = bn >> 4, n = bn & 15;
    int tx = threadIdx.x, ty = threadIdx.y;
    #pragma unroll
    for (int j = 0; j < 32; j += 8) {
        size_t idx = ((size_t)(j0 + ty + j)*BSZ + b)*H3 + 2*HID + n*64 + d0 + tx;
        tile[ty + j][tx] = hh[idx];
    }
    __syncthreads();
    #pragma unroll
    for (int j = 0; j < 32; j += 8) {
        size_t o = ((size_t)bn*DHEAD + d0 + ty + j)*KLEN + j0 + tx;
        vth[o] = tile[tx][ty + j];
    }
}

__global__ void k_bwk(const __half* __restrict__ hh,
                      const float* __restrict__ bias, float* __restrict__ bwk)
{
    int gid = blockIdx.x * 8 + (threadIdx.x >> 5);
    int lane = threadIdx.x & 31;
    int bn = gid >> 10, j = gid & 1023;
    int b = bn >> 4, n = bn & 15;
    size_t idx = ((size_t)j*BSZ + b)*H3 + HID + n*64 + lane*2;
    __half2 h2 = *(const __half2*)(hh + idx);
    float2 bv = *(const float2*)(bias + n*64 + lane*2);
    float v = __half2float(h2.x) * bv.x + __half2float(h2.y) * bv.y;
    #pragma unroll
    for (int o = 16; o > 0; o >>= 1) v += __shfl_down_sync(0xffffffffu, v, o);
    if (lane == 0) bwk[gid] = v;
}
__global__ void k_brr(const __half* __restrict__ rhh,
                      const float* __restrict__ bias, float* __restrict__ brr)
{
    int gid = blockIdx.x * 8 + (threadIdx.x >> 5);
    int lane = threadIdx.x & 31;
    int n = gid >> 10, j = gid & 1023;
    size_t idx = (size_t)j*HID + n*64 + lane*2;
    __half2 h2 = *(const __half2*)(rhh + idx);
    float2 bv = *(const float2*)(bias + n*64 + lane*2);
    float v = __half2float(h2.x) * bv.x + __half2float(h2.y) * bv.y;
    #pragma unroll
    for (int o = 16; o > 0; o >>= 1) v += __shfl_down_sync(0xffffffffu, v, o);
    if (lane == 0) brr[gid] = v;
}

__global__ void simple_gemm(const float* __restrict__ A, const float* __restrict__ B,
                            float* __restrict__ C, int M, int N, int K, int ldc)
{
    __shared__ float As[16][16];
    __shared__ float Bs[16][17];
    int tx = threadIdx.x, ty = threadIdx.y;
    int r = blockIdx.y*16 + ty;
    int c = blockIdx.x*16 + tx;
    float acc = 0.f;
    for (int k0 = 0; k0 < K; k0 += 16) {
        As[ty][tx] = (r < M && (k0+tx) < K) ? A[(size_t)r*K + k0 + tx] : 0.f;
        Bs[ty][tx] = ((k0+ty) < K && c < N) ? B[(size_t)(k0+ty)*N + c] : 0.f;
        __syncthreads();
        #pragma unroll
        for (int kk = 0; kk < 16; kk++) acc += As[ty][kk] * Bs[kk][tx];
        __syncthreads();
    }
    if (r < M && c < N) C[(size_t)r*ldc + c] = acc;
}

__global__ void k_zero(float* p, int n) {
    int i = blockIdx.x*256 + threadIdx.x;
    if (i < n) p[i] = 0.f;
}
__global__ void k_copy_role(const float* __restrict__ role, float* __restrict__ dst) {
    dst[blockIdx.x*256 + threadIdx.x] = role[blockIdx.x*128 + threadIdx.x];
}
__global__ void k_copy_theme(const float* __restrict__ te, float* __restrict__ dst) {
    dst[blockIdx.x*512 + threadIdx.x] = te[blockIdx.x*256 + threadIdx.x];
}
__global__ void k_posemb(float* __restrict__ pos) {
    int j = blockIdx.x;
    int c = threadIdx.x;
    float inv = powf(10000.f, -(float)c / 512.f);
    float s = (float)(KLEN - 1 - j) * inv;
    pos[(size_t)j*DM + c]       = sinf(s);
    pos[(size_t)j*DM + 512 + c] = cosf(s);
}
// key mask as bitmask: kbits[b*32 + w] bit l -> position k = w*32 + l
__global__ void k_kbits(const int* __restrict__ dec, unsigned* __restrict__ kbits)
{
    int gwarp = blockIdx.x * 8 + (threadIdx.x >> 5);   // 0..511
    int lane = threadIdx.x & 31;
    int b = gwarp >> 5, w = gwarp & 31;
    int k = w * 32 + lane;
    int bit = (k < MLEN) ? 1 : (dec[(k - MLEN)*BSZ + b] != 0 ? 1 : 0);
    unsigned word = __ballot_sync(0xffffffffu, bit);
    if (lane == 0) kbits[b*32 + w] = word;
}
__global__ __launch_bounds__(256) void k_embed(const int* __restrict__ dec,
                                               const float* __restrict__ wemb,
                                               float* __restrict__ x) {
    int row = blockIdx.x;
    int tok = dec[row];
    float4 v = *(const float4*)(wemb + (size_t)tok*DM + threadIdx.x*4);
    *(float4*)(x + (size_t)row*DM + threadIdx.x*4) = v;
}
__global__ __launch_bounds__(256) void k_mems_half(
    const float* __restrict__ mems_i, __half* __restrict__ AH)
{
    int row = blockIdx.x;
    float4 v = *(const float4*)(mems_i + (size_t)row*DM + threadIdx.x*4);
    size_t o = (size_t)row*DM + threadIdx.x*4;
    hf_write2(AH, o, v.x, v.y);
    hf_write2(AH, o + 2, v.z, v.w);
}

// ----- softmax: one warp per row, shuffle reductions, bitmask, incremental shift -----
__global__ __launch_bounds__(256) void k_softmax(
    const __half* __restrict__ scores, const __half* __restrict__ bdraw,
    const float* __restrict__ bwk, const float* __restrict__ brr,
    const unsigned* __restrict__ kbits, __half* __restrict__ ph)
{
    int gidx = blockIdx.x * 8 + (threadIdx.x >> 5);   // row id over NBN*QLEN
    int lane = threadIdx.x & 31;
    int bn = gidx >> 9;
    int q  = gidx & 511;
    int b  = bn >> 4, n = bn & 15;

    size_t rowbase = ((size_t)bn*QLEN + q)*KLEN;
    size_t bdbase  = (size_t)bn*QLEN*KLEN;

    // incremental rel_shift bookkeeping: f = 512 + q*1024 + k, k = 32u + lane
    int f0 = QLEN + q*KLEN + lane;
    int r = f0 / (KLEN+1);
    int c = f0 - r * (KLEN+1);

    float v[32];
    float m = -3.0e38f;
    #pragma unroll
    for (int u = 0; u < 32; u++) {
        int k = u*32 + lane;
        float s = __half2float(scores[rowbase + k]) + bwk[(size_t)bn*KLEN + k];
        float bd = (c == 0) ? 0.f
                 : __half2float(bdraw[bdbase + (size_t)r*KLEN + (c-1)]) + brr[n*KLEN + (c-1)];
        s = (s + bd) * 0.125f;
        if (!((kbits[b*32 + u] >> lane) & 1u)) s = -1e9f;
        v[u] = s;
        m = fmaxf(m, s);
        c += 32;
        if (c >= KLEN+1) { c -= KLEN+1; r++; }
    }
    #pragma unroll
    for (int o = 16; o > 0; o >>= 1)
        m = fmaxf(m, __shfl_xor_sync(0xffffffffu, m, o));
    float sum = 0.f;
    #pragma unroll
    for (int u = 0; u < 32; u++) { v[u] = __expf(v[u] - m); sum += v[u]; }
    #pragma unroll
    for (int o = 16; o > 0; o >>= 1)
        sum += __shfl_xor_sync(0xffffffffu, sum, o);
    float inv = 1.f / sum;
    #pragma unroll
    for (int u = 0; u < 32; u++)
        ph[rowbase + u*32 + lane] = __float2half_rn(v[u] * inv);
}

// ---------------- add + LayerNorm. OUT: 0 fp32; 1 fp32 + single fp16 ----
template<int OUT>
__global__ __launch_bounds__(256) void k_ln(
    const float* __restrict__ A, const float* __restrict__ B,
    const float* __restrict__ g, const float* __restrict__ be,
    float* __restrict__ O, __half* __restrict__ Ho)
{
    int row = blockIdx.x, tid = threadIdx.x;
    __shared__ float red[256];
    float4 v = *(const float4*)(A + (size_t)row*DM + tid*4);
    if (B) {
        float4 w = *(const float4*)(B + (size_t)row*DM + tid*4);
        v.x+=w.x; v.y+=w.y; v.z+=w.z; v.w+=w.w;
    }
    red[tid] = v.x+v.y+v.z+v.w; __syncthreads();
    for (int st = 128; st > 0; st >>= 1) {
        if (tid < st) red[tid] += red[tid+st];
        __syncthreads();
    }
    float mu = red[0] * (1.f/1024.f); __syncthreads();
    float dx=v.x-mu, dy=v.y-mu, dz=v.z-mu, dw=v.w-mu;
    red[tid] = dx*dx+dy*dy+dz*dz+dw*dw; __syncthreads();
    for (int st = 128; st > 0; st >>= 1) {
        if (tid < st) red[tid] += red[tid+st];
        __syncthreads();
    }
    float rstd = rsqrtf(red[0]*(1.f/1024.f) + 1e-3f);
    float4 gg = *(const float4*)(g + tid*4);
    float4 bb = *(const float4*)(be + tid*4);
    float o0 = dx*rstd*gg.x + bb.x;
    float o1 = dy*rstd*gg.y + bb.y;
    float o2 = dz*rstd*gg.z + bb.z;
    float o3 = dw*rstd*gg.w + bb.w;
    size_t idx = (size_t)row*DM + tid*4;
    float4 o = {o0, o1, o2, o3};
    *(float4*)(O + idx) = o;
    if (OUT == 1) {
        hf_write2(Ho, idx, o0, o1);
        hf_write2(Ho, idx + 2, o2, o3);
    }
}

// ---- fused LN_att + LN1 (t emitted as single fp16) ----
__global__ __launch_bounds__(256) void k_ln2(
    const float* __restrict__ X, const float* __restrict__ T,
    const float* __restrict__ g1, const float* __restrict__ b1,
    const float* __restrict__ g2, const float* __restrict__ b2,
    float* __restrict__ H, __half* __restrict__ Ho)
{
    int row = blockIdx.x, tid = threadIdx.x;
    __shared__ float red[256];
    float4 v = *(const float4*)(X + (size_t)row*DM + tid*4);
    {
        float4 w = *(const float4*)(T + (size_t)row*DM + tid*4);
        v.x+=w.x; v.y+=w.y; v.z+=w.z; v.w+=w.w;
    }
    red[tid] = v.x+v.y+v.z+v.w; __syncthreads();
    for (int st = 128; st > 0; st >>= 1) {
        if (tid < st) red[tid] += red[tid+st];
        __syncthreads();
    }
    float mu = red[0] * (1.f/1024.f); __syncthreads();
    float dx=v.x-mu, dy=v.y-mu, dz=v.z-mu, dw=v.w-mu;
    red[tid] = dx*dx+dy*dy+dz*dz+dw*dw; __syncthreads();
    for (int st = 128; st > 0; st >>= 1) {
        if (tid < st) red[tid] += red[tid+st];
        __syncthreads();
    }
    float rstd = rsqrtf(red[0]*(1.f/1024.f) + 1e-3f);
    __syncthreads();
    float4 gg = *(const float4*)(g1 + tid*4);
    float4 bb = *(const float4*)(b1 + tid*4);
    float h0 = dx*rstd*gg.x + bb.x;
    float h1 = dy*rstd*gg.y + bb.y;
    float h2 = dz*rstd*gg.z + bb.z;
    float h3 = dw*rstd*gg.w + bb.w;
    size_t idx = (size_t)row*DM + tid*4;
    float4 hv = {h0, h1, h2, h3};
    *(float4*)(H + idx) = hv;
    red[tid] = h0+h1+h2+h3; __syncthreads();
    for (int st = 128; st > 0; st >>= 1) {
        if (tid < st) red[tid] += red[tid+st];
        __syncthreads();
    }
    float mu2 = red[0] * (1.f/1024.f); __syncthreads();
    float ex=h0-mu2, ey=h1-mu2, ez=h2-mu2, ew=h3-mu2;
    red[tid] = ex*ex+ey*ey+ez*ez+ew*ew; __syncthreads();
    for (int st = 128; st > 0; st >>= 1) {
        if (tid < st) red[tid] += red[tid+st];
        __syncthreads();
    }
    float rstd2 = rsqrtf(red[0]*(1.f/1024.f) + 1e-3f);
    float4 g2v = *(const float4*)(g2 + tid*4);
    float4 b2v = *(const float4*)(b2 + tid*4);
    hf_write2(Ho, idx,     ex*rstd2*g2v.x + b2v.x, ey*rstd2*g2v.y + b2v.y);
    hf_write2(Ho, idx + 2, ez*rstd2*g2v.z + b2v.z, ew*rstd2*g2v.w + b2v.w);
}

// ---------------- pooling + logits ----------------
__global__ void k_pool(const int* __restrict__ dec, const float* __restrict__ x,
                       float* __restrict__ pooled)
{
    int b = blockIdx.x, c = threadIdx.x;
    float acc = 0.f;
    for (int q = 0; q < QLEN; q++)
        if (dec[q*BSZ + b] == 2)
            acc += x[((size_t)q*BSZ + b)*DM + c];
    pooled[b*DM + c] = acc;
}
__global__ void k_logits(const float* __restrict__ pooled,
                         const float* __restrict__ theme,
                         float* __restrict__ out)
{
    int t = blockIdx.x, b = blockIdx.y, tid = threadIdx.x;
    __shared__ float red[256];
    float4 p = *(const float4*)(pooled + (size_t)b*DM + tid*4);
    float4 w = *(const float4*)(theme + (size_t)t*DM + tid*4);
    red[tid] = p.x*w.x + p.y*w.y + p.z*w.z + p.w*w.w;
    __syncthreads();
    for (int st = 128; st > 0; st >>= 1) {
        if (tid < st) red[tid] += red[tid+st];
        __syncthreads();
    }
    if (tid == 0) out[b*THEME_SIZE + t] = red[0];
}

// ---------------- driver ----------------
extern "C" void kernel_launch(void* const* d_in, const int* in_sizes, int n_in,
                              void* d_out, int out_size) {
    const int*   dec      = (const int*)  d_in[0];
    const float* mems     = (const float*)d_in[1];
    const float* rel_t_r  = (const float*)d_in[2];
    const float* rel_r_f  = (const float*)d_in[3];
    const float* theme_e  = (const float*)d_in[4];
    const float* role_e   = (const float*)d_in[5];
    const float* form_e   = (const float*)d_in[6];
    const float* word_e   = (const float*)d_in[7];
    const float* theme_W  = (const float*)d_in[8];
    const float* theme_b  = (const float*)d_in[9];
    const float* r_w_bias = (const float*)d_in[10];
    const float* r_r_bias = (const float*)d_in[11];
    const float* qkv_W    = (const float*)d_in[12];
    const float* qkv_b    = (const float*)d_in[13];
    const float* r_W      = (const float*)d_in[14];
    const float* o_W      = (const float*)d_in[15];
    const float* o_b      = (const float*)d_in[16];
    const float* ln_att_g = (const float*)d_in[17];
    const float* ln_att_b = (const float*)d_in[18];
    const float* ln1_g    = (const float*)d_in[19];
    const float* ln1_b    = (const float*)d_in[20];
    const float* ffn_W1   = (const float*)d_in[21];
    const float* ffn_b1   = (const float*)d_in[22];
    const float* ffn_W2   = (const float*)d_in[23];
    const float* ffn_b2   = (const float*)d_in[24];
    const float* ln2_g    = (const float*)d_in[25];
    const float* ln2_b    = (const float*)d_in[26];
    float* out = (float*)d_out;

    float *pos, *x, *scoresF, *bdF, *h, *tmp;
    float *theme, *rolecat, *themecat, *pooled, *bwk, *brr;
    __half *ah, *al, *ah2, *bth, *hh, *rhh, *posh, *ph, *vth;
    unsigned *kbits;
    cudaGetSymbolAddress((void**)&pos, g_pos);
    cudaGetSymbolAddress((void**)&x, g_x);
    cudaGetSymbolAddress((void**)&scoresF, g_scores);
    cudaGetSymbolAddress((void**)&bdF, g_bdbuf);
    cudaGetSymbolAddress((void**)&h, g_h);
    cudaGetSymbolAddress((void**)&tmp, g_tmp);
    cudaGetSymbolAddress((void**)&theme, g_theme);
    cudaGetSymbolAddress((void**)&rolecat, g_rolecat);
    cudaGetSymbolAddress((void**)&themecat, g_themecat);
    cudaGetSymbolAddress((void**)&pooled, g_pooled);
    cudaGetSymbolAddress((void**)&kbits, g_kbits);
    cudaGetSymbolAddress((void**)&ah, g_ah);
    cudaGetSymbolAddress((void**)&al, g_al);
    cudaGetSymbolAddress((void**)&ah2, g_ah2);
    cudaGetSymbolAddress((void**)&bth, g_bth);
    cudaGetSymbolAddress((void**)&hh, g_hh);
    cudaGetSymbolAddress((void**)&rhh, g_rhh);
    cudaGetSymbolAddress((void**)&posh, g_posh);
    cudaGetSymbolAddress((void**)&ph, g_ph);
    cudaGetSymbolAddress((void**)&vth, g_vth);
    cudaGetSymbolAddress((void**)&bwk, g_bwk);
    cudaGetSymbolAddress((void**)&brr, g_brr);

    __half* scoresH = (__half*)scoresF;
    __half* bdH     = (__half*)bdF;

    cudaFuncSetAttribute(mma_gemm_theme, cudaFuncAttributeMaxDynamicSharedMemorySize, GSMEM3);
    cudaFuncSetAttribute(mma_gemm64<0,3>, cudaFuncAttributeMaxDynamicSharedMemorySize, GSMEM4);
    cudaFuncSetAttribute(mma_gemm64<0,0>, cudaFuncAttributeMaxDynamicSharedMemorySize, GSMEM4);
    cudaFuncSetAttribute(mma_gemm64<1,3>, cudaFuncAttributeMaxDynamicSharedMemorySize, GSMEM4);
    cudaFuncSetAttribute(k_score2, cudaFuncAttributeMaxDynamicSharedMemorySize, SC_SMEM);

    #define SPLIT_BT(src, Kk, Nn) k_split_bt<<<dim3((Nn)/32,(Kk)/32), dim3(32,8)>>>(src, bth, Kk, Nn)

    // ---- theme pipeline (keeps 2-pass precision through tanh) ----
    k_zero<<<(THEME_PAD*TCAT + 255)/256, 256>>>(themecat, THEME_PAD*TCAT);
    k_copy_role<<<64, 128>>>(role_e, rolecat);
    k_copy_theme<<<1000, 256>>>(theme_e, themecat);
    {
        dim3 blk(16,16), grd((128+15)/16, (64+15)/16);
        simple_gemm<<<grd, blk>>>(rel_r_f, form_e, rolecat + 128, 64, 128, 32, 256);
    }
    {
        dim3 blk(16,16), grd((256+15)/16, (1000+15)/16);
        simple_gemm<<<grd, blk>>>(rel_t_r, rolecat, themecat + 256, 1000, 256, 64, 512);
    }
    k_split_a<<<(THEME_PAD*TCAT)/1024, 256>>>(themecat, ah, al, THEME_PAD*TCAT);
    SPLIT_BT(theme_W, TCAT, DM);
    mma_gemm_theme<<<dim3(DM/128, THEME_PAD/128), 256, GSMEM3>>>(
        ah, al, bth, theme_b, theme, THEME_PAD, DM, TCAT, DM);

    // ---- setup ----
    k_posemb<<<KLEN, 512>>>(pos);
    k_tohalf<<<(KLEN*DM)/1024, 256>>>(pos, posh, KLEN*DM);
    k_kbits<<<64, 256>>>(dec, kbits);
    k_embed<<<NTOK, 256>>>(dec, word_e, x);
    k_tohalf<<<(NTOK*DM)/1024, 256>>>(x, ah + (size_t)NTOK*DM, NTOK*DM);

    // ---- layers ----
    for (int i = 0; i < 8; i++) {
        k_mems_half<<<NTOK, 256>>>(mems + (size_t)i*MLEN*BSZ*DM, ah);
        SPLIT_BT(qkv_W + (size_t)i*DM*H3, DM, H3);
        mma_gemm64<0,3><<<dim3(2048/128, KTOK/128), 256, GSMEM4>>>(
            ah, bth + (size_t)1024*DM,
            qkv_b + (size_t)i*H3 + 1024, nullptr, hh + 1024,
            KTOK, 2048, DM, H3);
        mma_gemm64<0,3><<<dim3(HID/128, NTOK/128), 256, GSMEM4>>>(
            ah + (size_t)NTOK*DM, bth,
            qkv_b + (size_t)i*H3, nullptr, hh + (size_t)NTOK*H3,
            NTOK, HID, DM, H3);

        SPLIT_BT(r_W + (size_t)i*DM*HID, DM, HID);
        mma_gemm64<0,3><<<dim3(HID/128, KLEN/128), 256, GSMEM4>>>(
            posh, bth, nullptr, nullptr, rhh, KLEN, HID, DM, HID);

        k_vt<<<dim3(KLEN/32, DHEAD/32, NBN), dim3(32,8)>>>(hh, vth);
        k_bwk<<<(NBN*KLEN)/8, 256>>>(hh, r_w_bias, bwk);
        k_brr<<<(NHEAD*KLEN)/8, 256>>>(rhh, r_r_bias, brr);

        k_score2<<<dim3(KLEN/128, QLEN/128, NBN), 256, SC_SMEM>>>(
            hh, rhh, scoresH, bdH);
        k_softmax<<<(NBN*QLEN)/8, 256>>>(scoresH, bdH, bwk, brr, kbits, ph);
        k_pv_mma<<<dim3(QLEN/128, NBN), 256>>>(ph, vth, ah);

        SPLIT_BT(o_W + (size_t)i*HID*DM, HID, DM);
        mma_gemm64<0,0><<<dim3(DM/128, NTOK/128), 256, GSMEM4>>>(
            ah, bth, o_b + (size_t)i*DM, tmp, nullptr, NTOK, DM, HID, DM);

        k_ln2<<<NTOK, 256>>>(x, tmp, ln_att_g + i*DM, ln_att_b + i*DM,
                             ln1_g + i*DM, ln1_b + i*DM, h, ah);

        SPLIT_BT(ffn_W1 + (size_t)i*DM*DI, DM, DI);
        mma_gemm64<1,3><<<dim3(DI/128, NTOK/128), 256, GSMEM4>>>(
            ah, bth, ffn_b1 + (size_t)i*DI, nullptr, ah2, NTOK, DI, DM, DI);

        SPLIT_BT(ffn_W2 + (size_t)i*DI*DM, DI, DM);
        mma_gemm64<0,0><<<dim3(DM/128, NTOK/128), 256, GSMEM4>>>(
            ah2, bth, ffn_b2 + (size_t)i*DM, tmp, nullptr, NTOK, DM, DI, DM);

        k_ln<1><<<NTOK, 256>>>(h, tmp, ln2_g + i*DM, ln2_b + i*DM, x,
                               ah + (size_t)NTOK*DM);
    }

    // ---- pooling + logits ----
    k_pool<<<BSZ, 1024>>>(dec, x, pooled);
    k_logits<<<dim3(THEME_SIZE, BSZ), 256>>>(pooled, theme, out);
}